// round 14
// baseline (speedup 1.0000x reference)
#include <cuda_runtime.h>
#include <cuda_fp16.h>
#include <math.h>
#include <stdint.h>

#define Bb   2
#define CIN  64
#define HIDc 128
#define C2   256
#define DDim 32
#define HHe  56
#define WWi  56
#define HW   3136
#define PP   100352

__device__ float g_xz [Bb*(size_t)C2*PP];
__device__ float g_x1c[Bb*(size_t)HIDc*PP];
__device__ float g_pool[Bb*HIDc*DDim];
__device__ float g_gate[Bb*HIDc*DDim];
// fully halo-padded fp16 x1: [b][dp 34][hp 60][cc 8][c2 8][ws 72] u32-pairs; pads stay zero
__device__ __align__(16) unsigned short g_dwP[(size_t)Bb*34*60*64*72*2];
// fp16 A-frag packed conv weights: [s 72][kw 3][mt 8][lane 32][v 4] u32
__device__ __align__(16) unsigned g_wTh[72*3072];
// fp16 A-frag packed W_in: [ks 4][mt 16][lane 32][v 4] u32
__device__ __align__(16) unsigned g_pA[8192];
// fp16 A-frag packed W_out: [mt 4][ks 8][lane 32][v 4] u32
__device__ __align__(16) unsigned g_fA[4096];
// mamba intermediates
__device__ float g_seq[Bb*DDim*HIDc];
__device__ float g_xr [Bb*DDim*256];
__device__ float g_z  [Bb*DDim*256];
__device__ float g_y  [Bb*DDim*256];

__device__ __forceinline__ float sigmoidf_(float x){ return 1.f/(1.f+expf(-x)); }
__device__ __forceinline__ unsigned s2u(const void* p){ unsigned a; asm("{ .reg .u64 t; cvta.to.shared.u64 t, %1; cvt.u32.u64 %0, t; }" : "=r"(a) : "l"(p)); return a; }
__device__ __forceinline__ void bwait(unsigned a, unsigned par){
    asm volatile("{\n\t.reg .pred P;\n\tLW%=:\n\tmbarrier.try_wait.parity.acquire.cta.shared::cta.b64 P, [%0], %1, 0x989680;\n\t@P bra.uni LD%=;\n\tbra.uni LW%=;\n\tLD%=:\n\t}" :: "r"(a), "r"(par) : "memory");
}
__device__ __forceinline__ void bulkcp(unsigned dst, const void* src, unsigned bytes, unsigned mbar){
    asm volatile("cp.async.bulk.shared::cluster.global.mbarrier::complete_tx::bytes [%0], [%1], %2, [%3];"
                 :: "r"(dst), "l"(src), "r"(bytes), "r"(mbar) : "memory");
}
__device__ __forceinline__ void mma16f(float* c, const uint4 a, unsigned b0, unsigned b1){
    asm volatile("mma.sync.aligned.m16n8k16.row.col.f32.f16.f16.f32 "
                 "{%0,%1,%2,%3}, {%4,%5,%6,%7}, {%8,%9}, {%0,%1,%2,%3};"
                 : "+f"(c[0]), "+f"(c[1]), "+f"(c[2]), "+f"(c[3])
                 : "r"(a.x), "r"(a.y), "r"(a.z), "r"(a.w), "r"(b0), "r"(b1));
}

// ---------------- K0: merged weight packers (conv Ws + W_in + W_out) ---------
__global__ __launch_bounds__(256)
void k_wpack(const float* __restrict__ Ws, const float* __restrict__ W_in,
             const float* __restrict__ W_out){
    int bid = blockIdx.x;
    if (bid < 864){
        int i = bid*256 + threadIdx.x;
        int v = i & 3, lane = (i >> 2) & 31, mt = (i >> 7) & 7, kw = (i >> 10) % 3, s2 = i / 3072;
        int kd = s2 / 24, kh = (s2 >> 3) % 3, cc = s2 & 7;
        int lq = lane >> 2, lr = lane & 3;
        int o  = mt*16 + lq + 8*(v & 1);
        int c0 = cc*16 + 2*lr + 8*(v >> 1);
        int t27 = kd*9 + kh*3 + kw;
        __half2 h = __floats2half2_rn(Ws[((size_t)o*HIDc + c0)*27 + t27],
                                      Ws[((size_t)o*HIDc + c0 + 1)*27 + t27]);
        g_wTh[i] = *(unsigned*)&h;
    } else if (bid < 896){
        int i = (bid - 864)*256 + threadIdx.x;
        int v = i & 3, lane = (i >> 2) & 31, mt = (i >> 7) & 15, ks = i >> 11;
        int o = mt*16 + (lane >> 2) + 8*(v & 1);
        int c = ks*16 + 2*(lane & 3) + 8*(v >> 1);
        __half2 h = __floats2half2_rn(W_in[o*CIN + c], W_in[o*CIN + c + 1]);
        g_pA[i] = *(unsigned*)&h;
    } else {
        int i = (bid - 896)*256 + threadIdx.x;
        int v = i & 3, lane = (i >> 2) & 31, ks = (i >> 7) & 7, mt = i >> 10;
        int o = mt*16 + (lane >> 2) + 8*(v & 1);
        int c = ks*16 + 2*(lane & 3) + 8*(v >> 1);
        __half2 h = __floats2half2_rn(W_out[o*HIDc + c], W_out[o*HIDc + c + 1]);
        g_fA[i] = *(unsigned*)&h;
    }
}

// ---------------- K1: proj_in via fp16 mma ----------------
__global__ __launch_bounds__(512)
void k_projT(const float* __restrict__ inp){
    extern __shared__ unsigned ps[];          // A 8192 u32 | B 4608 u32
    unsigned* sB = ps + 8192;
    uint4* sA4 = (uint4*)ps;
    int tid = threadIdx.x, lane = tid & 31, wid = tid >> 5;
    int lq = lane >> 2, lr = lane & 3;
    int mw = wid >> 2, nw = wid & 3;
    int b = blockIdx.y, p0 = blockIdx.x*128;
    const uint4* gA = (const uint4*)g_pA;
    for (int i = tid; i < 2048; i += 512) sA4[i] = gA[i];
    for (int i = tid; i < 4096; i += 512){
        int c2 = i >> 7, p = i & 127;
        float x0 = inp[((size_t)(b*CIN + 2*c2))*PP + p0 + p];
        float x1 = inp[((size_t)(b*CIN + 2*c2 + 1))*PP + p0 + p];
        __half2 h = __floats2half2_rn(x0, x1);
        sB[p*36 + c2] = *(unsigned*)&h;
    }
    __syncthreads();
    float acc[4][4][4];
#pragma unroll
    for (int t = 0; t < 4; t++)
#pragma unroll
        for (int nt = 0; nt < 4; nt++)
#pragma unroll
            for (int j = 0; j < 4; j++) acc[t][nt][j] = 0.f;
#pragma unroll
    for (int ks = 0; ks < 4; ks++){
        uint4 A[4];
#pragma unroll
        for (int t = 0; t < 4; t++) A[t] = sA4[(ks*16 + mw*4 + t)*32 + lane];
#pragma unroll
        for (int nt = 0; nt < 4; nt++){
            int pr = nw*32 + nt*8 + lq;
            unsigned b0 = sB[pr*36 + ks*8 + lr];
            unsigned b1 = sB[pr*36 + ks*8 + lr + 4];
#pragma unroll
            for (int t = 0; t < 4; t++) mma16f(acc[t][nt], A[t], b0, b1);
        }
    }
#pragma unroll
    for (int t = 0; t < 4; t++){
        int o = mw*64 + t*16 + lq;
        float* d0 = g_xz + ((size_t)(b*C2 + o))*PP + p0 + nw*32 + 2*lr;
#pragma unroll
        for (int nt = 0; nt < 4; nt++){
            float2 v0, v1;
            v0.x = acc[t][nt][0]; v0.y = acc[t][nt][1];
            v1.x = acc[t][nt][2]; v1.y = acc[t][nt][3];
            *(float2*)(d0 + nt*8) = v0;
            *(float2*)(d0 + (size_t)8*PP + nt*8) = v1;
        }
    }
}

// ---------------- K2: depthwise 3x3x3, rolling depth window ------------------
__global__ __launch_bounds__(256)
void k_dw(const float* __restrict__ W_dw){
    __shared__ float sp[3][60*58];
    __shared__ float red[8];
    int bid = blockIdx.x;
    int c = bid & 255, b = bid >> 8;
    int tid = threadIdx.x, lane = tid & 31, wid = tid >> 5;
    const float* src = g_xz + ((size_t)(b*C2 + c))*PP;
    float wv[27];
#pragma unroll
    for (int t = 0; t < 27; t++) wv[t] = W_dw[c*27 + t];

    auto load_plane = [&](int slot, int gd){
        if ((unsigned)gd < 32u){
            const float* p = src + gd*HW;
            for (int idx = tid; idx < 3480; idx += 256){
                int hh = idx / 60, ww = idx % 60;
                int gh = hh - 1, gw = ww - 1;
                float v = 0.f;
                if ((unsigned)gh < 56u && (unsigned)gw < 56u) v = p[gh*56 + gw];
                sp[slot][idx] = v;
            }
        } else {
            for (int idx = tid; idx < 3480; idx += 256) sp[slot][idx] = 0.f;
        }
    };
    load_plane(0, -1);
    load_plane(1, 0);
    load_plane(2, 1);

    int cidx = (c >> 4)*8 + ((c >> 1) & 7);
    bool isX1 = (c < HIDc);
    for (int d = 0; d < 32; d++){
        __syncthreads();
        float psum = 0.f;
        for (int idx = tid; idx < 784; idx += 256){
            int h = idx / 14, w0 = (idx % 14)*4;
            float a0 = 0.f, a1 = 0.f, a2 = 0.f, a3 = 0.f;
#pragma unroll
            for (int kd = 0; kd < 3; kd++){
                const float* pl = sp[(d + kd) % 3];
#pragma unroll
                for (int kh = 0; kh < 3; kh++){
                    const float* row = pl + (h + kh)*60 + w0;
                    float4 r03 = *(const float4*)row;
                    float2 r45 = *(const float2*)(row + 4);
                    float wA = wv[kd*9 + kh*3], wB = wv[kd*9 + kh*3 + 1], wC = wv[kd*9 + kh*3 + 2];
                    a0 += r03.x*wA + r03.y*wB + r03.z*wC;
                    a1 += r03.y*wA + r03.z*wB + r03.w*wC;
                    a2 += r03.z*wA + r03.w*wB + r45.x*wC;
                    a3 += r03.w*wA + r45.x*wB + r45.y*wC;
                }
            }
            if (isX1){
                size_t base = ((((size_t)((b*34 + d + 1)*60) + h + 1)*64 + cidx)*72 + w0 + 1)*2 + (c & 1);
                g_dwP[base]     = __half_as_ushort(__float2half_rn(a0));
                g_dwP[base + 2] = __half_as_ushort(__float2half_rn(a1));
                g_dwP[base + 4] = __half_as_ushort(__float2half_rn(a2));
                g_dwP[base + 6] = __half_as_ushort(__float2half_rn(a3));
            }
            psum += a0 + a1 + a2 + a3;
        }
        if (!isX1){
#pragma unroll
            for (int off = 16; off > 0; off >>= 1) psum += __shfl_xor_sync(0xffffffffu, psum, off);
            if (lane == 0) red[wid] = psum;
            __syncthreads();
            if (tid == 0){
                float s = 0.f;
#pragma unroll
                for (int i = 0; i < 8; i++) s += red[i];
                g_pool[(b*HIDc + (c - HIDc))*DDim + d] = s * (1.f/HW);
            }
        }
        __syncthreads();
        load_plane(d % 3, d + 2);
    }
}

// ---------------- mamba chain ----------------
__global__ __launch_bounds__(256)
void k_m1(const float* __restrict__ W_t1){
    int idx = blockIdx.x*256 + threadIdx.x;
    int i = idx & 127, t = (idx >> 7) & 31, b = idx >> 12;
    const float* w  = W_t1 + i*HIDc;
    const float* pl = g_pool + b*HIDc*DDim + t;
    float a = 0.f;
    for (int c = 0; c < HIDc; c++) a += w[c] * pl[c*DDim];
    g_seq[idx] = a;
}

__global__ __launch_bounds__(256)
void k_m2(const float* __restrict__ in_w){
    __shared__ float s[HIDc];
    int blk = blockIdx.x, tid = threadIdx.x;
    int half = blk & 1, t = (blk >> 1) & 31, b = blk >> 6;
    if (tid < HIDc) s[tid] = g_seq[(b*DDim + t)*HIDc + tid];
    __syncthreads();
    int j = half*256 + tid;
    const float* w = in_w + (size_t)j*HIDc;
    float a = 0.f;
#pragma unroll 4
    for (int i = 0; i < HIDc; i++) a += s[i]*w[i];
    if (half == 0) g_xr[(b*DDim + t)*256 + tid] = a;
    else           g_z [(b*DDim + t)*256 + tid] = a;
}

__global__ __launch_bounds__(256)
void k_m3(const float* __restrict__ conv_w, const float* __restrict__ conv_b,
          const float* __restrict__ x_w, const float* __restrict__ dt_w,
          const float* __restrict__ dt_b, const float* __restrict__ A_log,
          const float* __restrict__ Dp){
    extern __shared__ float sm[];
    float* s_x    = sm;
    float* s_proj = sm + 8192;
    float* s_u    = sm + 9472;
    int b = blockIdx.x, tid = threadIdx.x;
    for (int i = tid; i < 40*256; i += 256) s_u[i] = x_w[i];
    __syncthreads();
    for (int idx = tid; idx < DDim*256; idx += 256){
        int t = idx >> 8, j = idx & 255;
        float a = conv_b[j];
#pragma unroll
        for (int k = 0; k < 4; k++){
            int tt = t + k - 3;
            if (tt >= 0) a += g_xr[(b*DDim + tt)*256 + j] * conv_w[j*4 + k];
        }
        s_x[idx] = a * sigmoidf_(a);
    }
    __syncthreads();
    for (int idx = tid; idx < DDim*40; idx += 256){
        int t = idx / 40, q = idx % 40;
        float a = 0.f;
        const float* u = s_x + t*256;
        const float* w = s_u + q*256;
        for (int j = 0; j < 256; j++) a += u[j]*w[j];
        s_proj[idx] = a;
    }
    __syncthreads();
    for (int idx = tid; idx < DDim*256; idx += 256){
        int t = idx >> 8, j = idx & 255;
        float a = dt_b[j];
#pragma unroll
        for (int r = 0; r < 8; r++) a += s_proj[t*40 + r]*dt_w[j*8 + r];
        s_u[idx] = (a > 20.f) ? a : log1pf(expf(a));
    }
    __syncthreads();
    {
        int dch = tid;
        float A[16], h[16];
#pragma unroll
        for (int n = 0; n < 16; n++){ A[n] = -expf(A_log[dch*16 + n]); h[n] = 0.f; }
        float Dv = Dp[dch];
        for (int t = 0; t < DDim; t++){
            float dtv = s_u[t*256 + dch];
            float xv  = s_x[t*256 + dch];
            float y = 0.f;
#pragma unroll
            for (int n = 0; n < 16; n++){
                float dA = expf(dtv * A[n]);
                h[n] = dA*h[n] + dtv * s_proj[t*40 + 8 + n] * xv;
                y += h[n] * s_proj[t*40 + 24 + n];
            }
            y += xv * Dv;
            float zv = g_z[(b*DDim + t)*256 + dch];
            y *= zv * sigmoidf_(zv);
            g_y[(b*DDim + t)*256 + dch] = y;
        }
    }
}

__global__ __launch_bounds__(128)
void k_m4(const float* __restrict__ out_w, const float* __restrict__ W_t2){
    __shared__ float sy[256];
    __shared__ float som[HIDc];
    int bt = blockIdx.x, tid = threadIdx.x;
    int b = bt >> 5, t = bt & 31;
    sy[tid]       = g_y[bt*256 + tid];
    sy[tid + 128] = g_y[bt*256 + 128 + tid];
    __syncthreads();
    {
        const float* w = out_w + (size_t)tid*256;
        float a = 0.f;
#pragma unroll 4
        for (int j = 0; j < 256; j++) a += sy[j]*w[j];
        som[tid] = a;
    }
    __syncthreads();
    {
        const float* w = W_t2 + (size_t)tid*HIDc;
        float a = 0.f;
#pragma unroll 4
        for (int c = 0; c < HIDc; c++) a += som[c]*w[c];
        g_gate[(b*HIDc + tid)*DDim + t] = sigmoidf_(a);
    }
}

// ---------------- K4: fp16 mma conv, 4-deep ring, 2 CTAs/SM ------------------
#define INBOFF 12288
#define BUFB   21504
__global__ __launch_bounds__(512, 2)
void k_conv_mma(){
    extern __shared__ __align__(128) char smem[];
    __shared__ __align__(8) unsigned long long mbars[4];
    unsigned usb = s2u(smem);
    unsigned umb = s2u(mbars);
    int tid = threadIdx.x, lane = tid & 31, wid = tid >> 5;
    int lq = lane >> 2, lr = lane & 3;
    int mw = wid >> 2, nw = wid & 3;
    int bid = blockIdx.x;
    int ht = bid % 14, d = (bid/14) & 31, b = bid / (14*32);
    int h0 = ht * 4;

    if (tid == 0){
#pragma unroll
        for (int i = 0; i < 4; i++)
            asm volatile("mbarrier.init.shared.b64 [%0], 1;" :: "r"(umb + i*8) : "memory");
    }
    __syncthreads();

    auto issue = [&](int s){
        int buf = s & 3;
        int cc = s & 7, kh = (s >> 3) % 3, kd = s / 24;
        if (tid == 0)
            asm volatile("mbarrier.arrive.expect_tx.shared.b64 _, [%0], %1;"
                         :: "r"(umb + buf*8), "r"(21504u) : "memory");
        if (tid < 4){
            int r = tid;
            const unsigned* src = (const unsigned*)g_dwP +
                (((size_t)(b*34 + d + kd)*60 + (h0 + kh + r))*64 + cc*8)*72;
            bulkcp(usb + (unsigned)(buf*BUFB + INBOFF + r*2304), src, 2304u, umb + buf*8);
        } else if (tid == 4){
            bulkcp(usb + (unsigned)(buf*BUFB), g_wTh + (size_t)s*3072, 12288u, umb + buf*8);
        }
    };

    float acc[2][7][4];
#pragma unroll
    for (int t = 0; t < 2; t++)
#pragma unroll
        for (int nt = 0; nt < 7; nt++)
#pragma unroll
            for (int j = 0; j < 4; j++) acc[t][nt][j] = 0.f;

    issue(0); issue(1); issue(2);
    for (int s = 0; s < 72; s++){
        if (s + 3 < 72) issue(s + 3);
        bwait(umb + (s&3)*8, (unsigned)((s >> 2) & 1));
        const char* buf = smem + (s&3)*BUFB;
        const uint4* wp = (const uint4*)buf;
        const unsigned* ibl = (const unsigned*)(buf + INBOFF) + (nw*8 + lr)*72 + lq;
#pragma unroll
        for (int kw = 0; kw < 3; kw++){
            uint4 A0 = wp[(kw*8 + mw*2    )*32 + lane];
            uint4 A1 = wp[(kw*8 + mw*2 + 1)*32 + lane];
#pragma unroll
            for (int nt = 0; nt < 7; nt++){
                unsigned b0 = ibl[nt*8 + kw];
                unsigned b1 = ibl[nt*8 + kw + 288];
                mma16f(acc[0][nt], A0, b0, b1);
                mma16f(acc[1][nt], A1, b0, b1);
            }
        }
        __syncthreads();
    }

    int h = h0 + nw;
#pragma unroll
    for (int t = 0; t < 2; t++){
        int o = (mw*2 + t)*16 + lq;
        float* base0 = g_x1c + ((size_t)(b*HIDc + o))*PP + (size_t)d*HW + h*56;
#pragma unroll
        for (int nt = 0; nt < 7; nt++){
            int w = nt*8 + 2*lr;
            float2 v0, v1;
            v0.x = fmaxf(acc[t][nt][0], 0.f); v0.y = fmaxf(acc[t][nt][1], 0.f);
            v1.x = fmaxf(acc[t][nt][2], 0.f); v1.y = fmaxf(acc[t][nt][3], 0.f);
            *(float2*)(base0 + w) = v0;
            *(float2*)(base0 + (size_t)8*PP + w) = v1;
        }
    }
}

// ---------------- K5: gate + proj_out via fp16 mma ----------------
#define FPAD 132
__global__ __launch_bounds__(256)
void k_final(float* __restrict__ out){
    __shared__ unsigned short sf[128*FPAD];
    int tid = threadIdx.x, lane = tid & 31, wid = tid >> 5;
    int lq = lane >> 2, lr = lane & 3;
    int mw = wid >> 2, nw = wid & 3;
    int b = blockIdx.y;
    int p0 = blockIdx.x*128;
    for (int i = tid; i < 16384; i += 256){
        int c = i >> 7, p = i & 127;
        int gp = p0 + p;
        int d = gp / HW;
        float v = g_x1c[((size_t)(b*HIDc + c))*PP + gp] * g_gate[(b*HIDc + c)*DDim + d];
        sf[c*FPAD + p] = __half_as_ushort(__float2half_rn(v));
    }
    __syncthreads();
    float acc[2][4][4];
#pragma unroll
    for (int t = 0; t < 2; t++)
#pragma unroll
        for (int nt = 0; nt < 4; nt++)
#pragma unroll
            for (int j = 0; j < 4; j++) acc[t][nt][j] = 0.f;
    const uint4* gA = (const uint4*)g_fA;
#pragma unroll
    for (int ks = 0; ks < 8; ks++){
        uint4 A0 = gA[((mw*2    )*8 + ks)*32 + lane];
        uint4 A1 = gA[((mw*2 + 1)*8 + ks)*32 + lane];
#pragma unroll
        for (int nt = 0; nt < 4; nt++){
            int p = nw*32 + nt*8 + lq;
            int c0 = ks*16 + 2*lr;
            unsigned b0 = (unsigned)sf[c0*FPAD + p]       | ((unsigned)sf[(c0+1)*FPAD + p] << 16);
            unsigned b1 = (unsigned)sf[(c0+8)*FPAD + p]   | ((unsigned)sf[(c0+9)*FPAD + p] << 16);
            mma16f(acc[0][nt], A0, b0, b1);
            mma16f(acc[1][nt], A1, b0, b1);
        }
    }
#pragma unroll
    for (int t = 0; t < 2; t++){
        int o = mw*32 + t*16 + lq;
        float* base = out + ((size_t)(b*64 + o))*PP + p0 + nw*32 + 2*lr;
#pragma unroll
        for (int nt = 0; nt < 4; nt++){
            float2 v0, v1;
            v0.x = acc[t][nt][0]; v0.y = acc[t][nt][1];
            v1.x = acc[t][nt][2]; v1.y = acc[t][nt][3];
            *(float2*)(base + nt*8) = v0;
            *(float2*)(base + (size_t)8*PP + nt*8) = v1;
        }
    }
}

// ---------------- launch ----------------
extern "C" void kernel_launch(void* const* d_in, const int* in_sizes, int n_in,
                              void* d_out, int out_size){
    const float* inp      = (const float*)d_in[0];
    const float* W_in     = (const float*)d_in[1];
    const float* W_dw     = (const float*)d_in[2];
    const float* W_s      = (const float*)d_in[3];
    const float* W_t1     = (const float*)d_in[4];
    const float* W_t2     = (const float*)d_in[5];
    const float* m_in_w   = (const float*)d_in[6];
    const float* m_conv_w = (const float*)d_in[7];
    const float* m_conv_b = (const float*)d_in[8];
    const float* m_x_w    = (const float*)d_in[9];
    const float* m_dt_w   = (const float*)d_in[10];
    const float* m_dt_b   = (const float*)d_in[11];
    const float* m_A_log  = (const float*)d_in[12];
    const float* m_D      = (const float*)d_in[13];
    const float* m_out_w  = (const float*)d_in[14];
    const float* W_out    = (const float*)d_in[15];
    float* out = (float*)d_out;

    cudaFuncSetAttribute(k_projT, cudaFuncAttributeMaxDynamicSharedMemorySize, 51200);
    cudaFuncSetAttribute(k_m3,    cudaFuncAttributeMaxDynamicSharedMemorySize, 19712*4);
    cudaFuncSetAttribute(k_conv_mma, cudaFuncAttributeMaxDynamicSharedMemorySize, 4*BUFB);

    k_wpack   <<<912, 256>>>(W_s, W_in, W_out);                   // idx 0
    k_projT   <<<dim3(784, Bb), 512, 51200>>>(inp);               // idx 1
    k_dw      <<<Bb*C2, 256>>>(W_dw);                             // idx 2
    k_conv_mma<<<Bb*DDim*14, 512, 4*BUFB>>>();                    // idx 3 (profiled slot)
    k_m1      <<<32, 256>>>(W_t1);
    k_m2      <<<128, 256>>>(m_in_w);
    k_m3      <<<Bb, 256, 19712*4>>>(m_conv_w, m_conv_b, m_x_w, m_dt_w,
                                     m_dt_b, m_A_log, m_D);
    k_m4      <<<64, 128>>>(m_out_w, W_t2);
    k_final   <<<dim3(784, Bb), 256>>>(out);
}

// round 15
// speedup vs baseline: 1.4662x; 1.4662x over previous
#include <cuda_runtime.h>
#include <cuda_fp16.h>
#include <math.h>
#include <stdint.h>

#define Bb   2
#define CIN  64
#define HIDc 128
#define C2   256
#define DDim 32
#define HHe  56
#define WWi  56
#define HW   3136
#define PP   100352

__device__ float g_xz [Bb*(size_t)C2*PP];
__device__ float g_x1c[Bb*(size_t)HIDc*PP];
__device__ float g_pool[Bb*HIDc*DDim];
__device__ float g_gate[Bb*HIDc*DDim];
// fully halo-padded fp16 x1: [b][dp 34][hp 60][cc 8][c2 8][ws 72] u32-pairs; pads stay zero
__device__ __align__(16) unsigned short g_dwP[(size_t)Bb*34*60*64*72*2];
// fp16 A-frag packed conv weights: [s2 72][kw 3][mt 8][lane 32][v 4] u32
__device__ __align__(16) unsigned g_wTh[72*3072];
// fp16 A-frag packed W_in: [ks 4][mt 16][lane 32][v 4] u32
__device__ __align__(16) unsigned g_pA[8192];
// fp16 A-frag packed W_out: [mt 4][ks 8][lane 32][v 4] u32
__device__ __align__(16) unsigned g_fA[4096];
// mamba intermediates
__device__ float g_seq[Bb*DDim*HIDc];
__device__ float g_xr [Bb*DDim*256];
__device__ float g_z  [Bb*DDim*256];
__device__ float g_y  [Bb*DDim*256];

__device__ __forceinline__ float sigmoidf_(float x){ return 1.f/(1.f+expf(-x)); }
__device__ __forceinline__ unsigned s2u(const void* p){ unsigned a; asm("{ .reg .u64 t; cvta.to.shared.u64 t, %1; cvt.u32.u64 %0, t; }" : "=r"(a) : "l"(p)); return a; }
__device__ __forceinline__ void bwait(unsigned a, unsigned par){
    asm volatile("{\n\t.reg .pred P;\n\tLW%=:\n\tmbarrier.try_wait.parity.acquire.cta.shared::cta.b64 P, [%0], %1, 0x989680;\n\t@P bra.uni LD%=;\n\tbra.uni LW%=;\n\tLD%=:\n\t}" :: "r"(a), "r"(par) : "memory");
}
__device__ __forceinline__ void bulkcp(unsigned dst, const void* src, unsigned bytes, unsigned mbar){
    asm volatile("cp.async.bulk.shared::cluster.global.mbarrier::complete_tx::bytes [%0], [%1], %2, [%3];"
                 :: "r"(dst), "l"(src), "r"(bytes), "r"(mbar) : "memory");
}
__device__ __forceinline__ void mma16f(float* c, const uint4 a, unsigned b0, unsigned b1){
    asm volatile("mma.sync.aligned.m16n8k16.row.col.f32.f16.f16.f32 "
                 "{%0,%1,%2,%3}, {%4,%5,%6,%7}, {%8,%9}, {%0,%1,%2,%3};"
                 : "+f"(c[0]), "+f"(c[1]), "+f"(c[2]), "+f"(c[3])
                 : "r"(a.x), "r"(a.y), "r"(a.z), "r"(a.w), "r"(b0), "r"(b1));
}

// ---------------- K0: merged weight packers (conv Ws + W_in + W_out) ---------
__global__ __launch_bounds__(256)
void k_wpack(const float* __restrict__ Ws, const float* __restrict__ W_in,
             const float* __restrict__ W_out){
    int bid = blockIdx.x;
    if (bid < 864){
        int i = bid*256 + threadIdx.x;
        int v = i & 3, lane = (i >> 2) & 31, mt = (i >> 7) & 7, kw = (i >> 10) % 3, s2 = i / 3072;
        int kd = s2 / 24, kh = (s2 >> 3) % 3, cc = s2 & 7;
        int lq = lane >> 2, lr = lane & 3;
        int o  = mt*16 + lq + 8*(v & 1);
        int c0 = cc*16 + 2*lr + 8*(v >> 1);
        int t27 = kd*9 + kh*3 + kw;
        __half2 h = __floats2half2_rn(Ws[((size_t)o*HIDc + c0)*27 + t27],
                                      Ws[((size_t)o*HIDc + c0 + 1)*27 + t27]);
        g_wTh[i] = *(unsigned*)&h;
    } else if (bid < 896){
        int i = (bid - 864)*256 + threadIdx.x;
        int v = i & 3, lane = (i >> 2) & 31, mt = (i >> 7) & 15, ks = i >> 11;
        int o = mt*16 + (lane >> 2) + 8*(v & 1);
        int c = ks*16 + 2*(lane & 3) + 8*(v >> 1);
        __half2 h = __floats2half2_rn(W_in[o*CIN + c], W_in[o*CIN + c + 1]);
        g_pA[i] = *(unsigned*)&h;
    } else {
        int i = (bid - 896)*256 + threadIdx.x;
        int v = i & 3, lane = (i >> 2) & 31, ks = (i >> 7) & 7, mt = i >> 10;
        int o = mt*16 + (lane >> 2) + 8*(v & 1);
        int c = ks*16 + 2*(lane & 3) + 8*(v >> 1);
        __half2 h = __floats2half2_rn(W_out[o*HIDc + c], W_out[o*HIDc + c + 1]);
        g_fA[i] = *(unsigned*)&h;
    }
}

// ---------------- K1: proj_in via fp16 mma ----------------
__global__ __launch_bounds__(512)
void k_projT(const float* __restrict__ inp){
    extern __shared__ unsigned ps[];          // A 8192 u32 | B 4608 u32
    unsigned* sB = ps + 8192;
    uint4* sA4 = (uint4*)ps;
    int tid = threadIdx.x, lane = tid & 31, wid = tid >> 5;
    int lq = lane >> 2, lr = lane & 3;
    int mw = wid >> 2, nw = wid & 3;
    int b = blockIdx.y, p0 = blockIdx.x*128;
    const uint4* gA = (const uint4*)g_pA;
    for (int i = tid; i < 2048; i += 512) sA4[i] = gA[i];
    for (int i = tid; i < 4096; i += 512){
        int c2 = i >> 7, p = i & 127;
        float x0 = inp[((size_t)(b*CIN + 2*c2))*PP + p0 + p];
        float x1 = inp[((size_t)(b*CIN + 2*c2 + 1))*PP + p0 + p];
        __half2 h = __floats2half2_rn(x0, x1);
        sB[p*36 + c2] = *(unsigned*)&h;
    }
    __syncthreads();
    float acc[4][4][4];
#pragma unroll
    for (int t = 0; t < 4; t++)
#pragma unroll
        for (int nt = 0; nt < 4; nt++)
#pragma unroll
            for (int j = 0; j < 4; j++) acc[t][nt][j] = 0.f;
#pragma unroll
    for (int ks = 0; ks < 4; ks++){
        uint4 A[4];
#pragma unroll
        for (int t = 0; t < 4; t++) A[t] = sA4[(ks*16 + mw*4 + t)*32 + lane];
#pragma unroll
        for (int nt = 0; nt < 4; nt++){
            int pr = nw*32 + nt*8 + lq;
            unsigned b0 = sB[pr*36 + ks*8 + lr];
            unsigned b1 = sB[pr*36 + ks*8 + lr + 4];
#pragma unroll
            for (int t = 0; t < 4; t++) mma16f(acc[t][nt], A[t], b0, b1);
        }
    }
#pragma unroll
    for (int t = 0; t < 4; t++){
        int o = mw*64 + t*16 + lq;
        float* d0 = g_xz + ((size_t)(b*C2 + o))*PP + p0 + nw*32 + 2*lr;
#pragma unroll
        for (int nt = 0; nt < 4; nt++){
            float2 v0, v1;
            v0.x = acc[t][nt][0]; v0.y = acc[t][nt][1];
            v1.x = acc[t][nt][2]; v1.y = acc[t][nt][3];
            *(float2*)(d0 + nt*8) = v0;
            *(float2*)(d0 + (size_t)8*PP + nt*8) = v1;
        }
    }
}

// ---------------- K2: depthwise 3x3x3, rolling depth window ------------------
__global__ __launch_bounds__(256)
void k_dw(const float* __restrict__ W_dw){
    __shared__ float sp[3][60*58];
    __shared__ float red[8];
    int bid = blockIdx.x;
    int c = bid & 255, b = bid >> 8;
    int tid = threadIdx.x, lane = tid & 31, wid = tid >> 5;
    const float* src = g_xz + ((size_t)(b*C2 + c))*PP;
    float wv[27];
#pragma unroll
    for (int t = 0; t < 27; t++) wv[t] = W_dw[c*27 + t];

    auto load_plane = [&](int slot, int gd){
        if ((unsigned)gd < 32u){
            const float* p = src + gd*HW;
            for (int idx = tid; idx < 3480; idx += 256){
                int hh = idx / 60, ww = idx % 60;
                int gh = hh - 1, gw = ww - 1;
                float v = 0.f;
                if ((unsigned)gh < 56u && (unsigned)gw < 56u) v = p[gh*56 + gw];
                sp[slot][idx] = v;
            }
        } else {
            for (int idx = tid; idx < 3480; idx += 256) sp[slot][idx] = 0.f;
        }
    };
    load_plane(0, -1);
    load_plane(1, 0);
    load_plane(2, 1);

    int cidx = (c >> 4)*8 + ((c >> 1) & 7);
    bool isX1 = (c < HIDc);
    for (int d = 0; d < 32; d++){
        __syncthreads();
        float psum = 0.f;
        for (int idx = tid; idx < 784; idx += 256){
            int h = idx / 14, w0 = (idx % 14)*4;
            float a0 = 0.f, a1 = 0.f, a2 = 0.f, a3 = 0.f;
#pragma unroll
            for (int kd = 0; kd < 3; kd++){
                const float* pl = sp[(d + kd) % 3];
#pragma unroll
                for (int kh = 0; kh < 3; kh++){
                    const float* row = pl + (h + kh)*60 + w0;
                    float4 r03 = *(const float4*)row;
                    float2 r45 = *(const float2*)(row + 4);
                    float wA = wv[kd*9 + kh*3], wB = wv[kd*9 + kh*3 + 1], wC = wv[kd*9 + kh*3 + 2];
                    a0 += r03.x*wA + r03.y*wB + r03.z*wC;
                    a1 += r03.y*wA + r03.z*wB + r03.w*wC;
                    a2 += r03.z*wA + r03.w*wB + r45.x*wC;
                    a3 += r03.w*wA + r45.x*wB + r45.y*wC;
                }
            }
            if (isX1){
                size_t base = ((((size_t)((b*34 + d + 1)*60) + h + 1)*64 + cidx)*72 + w0 + 1)*2 + (c & 1);
                g_dwP[base]     = __half_as_ushort(__float2half_rn(a0));
                g_dwP[base + 2] = __half_as_ushort(__float2half_rn(a1));
                g_dwP[base + 4] = __half_as_ushort(__float2half_rn(a2));
                g_dwP[base + 6] = __half_as_ushort(__float2half_rn(a3));
            }
            psum += a0 + a1 + a2 + a3;
        }
        if (!isX1){
#pragma unroll
            for (int off = 16; off > 0; off >>= 1) psum += __shfl_xor_sync(0xffffffffu, psum, off);
            if (lane == 0) red[wid] = psum;
            __syncthreads();
            if (tid == 0){
                float s = 0.f;
#pragma unroll
                for (int i = 0; i < 8; i++) s += red[i];
                g_pool[(b*HIDc + (c - HIDc))*DDim + d] = s * (1.f/HW);
            }
        }
        __syncthreads();
        load_plane(d % 3, d + 2);
    }
}

// ---------------- mamba chain ----------------
__global__ __launch_bounds__(256)
void k_m1(const float* __restrict__ W_t1){
    int idx = blockIdx.x*256 + threadIdx.x;
    int i = idx & 127, t = (idx >> 7) & 31, b = idx >> 12;
    const float* w  = W_t1 + i*HIDc;
    const float* pl = g_pool + b*HIDc*DDim + t;
    float a = 0.f;
    for (int c = 0; c < HIDc; c++) a += w[c] * pl[c*DDim];
    g_seq[idx] = a;
}

__global__ __launch_bounds__(256)
void k_m2(const float* __restrict__ in_w){
    __shared__ float s[HIDc];
    int blk = blockIdx.x, tid = threadIdx.x;
    int half = blk & 1, t = (blk >> 1) & 31, b = blk >> 6;
    if (tid < HIDc) s[tid] = g_seq[(b*DDim + t)*HIDc + tid];
    __syncthreads();
    int j = half*256 + tid;
    const float* w = in_w + (size_t)j*HIDc;
    float a = 0.f;
#pragma unroll 4
    for (int i = 0; i < HIDc; i++) a += s[i]*w[i];
    if (half == 0) g_xr[(b*DDim + t)*256 + tid] = a;
    else           g_z [(b*DDim + t)*256 + tid] = a;
}

__global__ __launch_bounds__(256)
void k_m3(const float* __restrict__ conv_w, const float* __restrict__ conv_b,
          const float* __restrict__ x_w, const float* __restrict__ dt_w,
          const float* __restrict__ dt_b, const float* __restrict__ A_log,
          const float* __restrict__ Dp){
    extern __shared__ float sm[];
    float* s_x    = sm;
    float* s_proj = sm + 8192;
    float* s_u    = sm + 9472;
    int b = blockIdx.x, tid = threadIdx.x;
    for (int i = tid; i < 40*256; i += 256) s_u[i] = x_w[i];
    __syncthreads();
    for (int idx = tid; idx < DDim*256; idx += 256){
        int t = idx >> 8, j = idx & 255;
        float a = conv_b[j];
#pragma unroll
        for (int k = 0; k < 4; k++){
            int tt = t + k - 3;
            if (tt >= 0) a += g_xr[(b*DDim + tt)*256 + j] * conv_w[j*4 + k];
        }
        s_x[idx] = a * sigmoidf_(a);
    }
    __syncthreads();
    for (int idx = tid; idx < DDim*40; idx += 256){
        int t = idx / 40, q = idx % 40;
        float a = 0.f;
        const float* u = s_x + t*256;
        const float* w = s_u + q*256;
        for (int j = 0; j < 256; j++) a += u[j]*w[j];
        s_proj[idx] = a;
    }
    __syncthreads();
    for (int idx = tid; idx < DDim*256; idx += 256){
        int t = idx >> 8, j = idx & 255;
        float a = dt_b[j];
#pragma unroll
        for (int r = 0; r < 8; r++) a += s_proj[t*40 + r]*dt_w[j*8 + r];
        s_u[idx] = (a > 20.f) ? a : log1pf(expf(a));
    }
    __syncthreads();
    {
        int dch = tid;
        float A[16], h[16];
#pragma unroll
        for (int n = 0; n < 16; n++){ A[n] = -expf(A_log[dch*16 + n]); h[n] = 0.f; }
        float Dv = Dp[dch];
        for (int t = 0; t < DDim; t++){
            float dtv = s_u[t*256 + dch];
            float xv  = s_x[t*256 + dch];
            float y = 0.f;
#pragma unroll
            for (int n = 0; n < 16; n++){
                float dA = expf(dtv * A[n]);
                h[n] = dA*h[n] + dtv * s_proj[t*40 + 8 + n] * xv;
                y += h[n] * s_proj[t*40 + 24 + n];
            }
            y += xv * Dv;
            float zv = g_z[(b*DDim + t)*256 + dch];
            y *= zv * sigmoidf_(zv);
            g_y[(b*DDim + t)*256 + dch] = y;
        }
    }
}

__global__ __launch_bounds__(128)
void k_m4(const float* __restrict__ out_w, const float* __restrict__ W_t2){
    __shared__ float sy[256];
    __shared__ float som[HIDc];
    int bt = blockIdx.x, tid = threadIdx.x;
    int b = bt >> 5, t = bt & 31;
    sy[tid]       = g_y[bt*256 + tid];
    sy[tid + 128] = g_y[bt*256 + 128 + tid];
    __syncthreads();
    {
        const float* w = out_w + (size_t)tid*256;
        float a = 0.f;
#pragma unroll 4
        for (int j = 0; j < 256; j++) a += sy[j]*w[j];
        som[tid] = a;
    }
    __syncthreads();
    {
        const float* w = W_t2 + (size_t)tid*HIDc;
        float a = 0.f;
#pragma unroll 4
        for (int c = 0; c < HIDc; c++) a += som[c]*w[c];
        g_gate[(b*HIDc + tid)*DDim + t] = sigmoidf_(a);
    }
}

// ---------------- K4: fp16 mma conv, merged 32-ch stages (36 stages) ---------
// Stage s in [0,36): ccg = s&3 (32 channels), kh = (s>>2)%3, kd = s/12.
// Buffer: [weights 24576B (2 s2-blocks)][input 4 rows x 16ch x 72 u32 = 18432B]
#define INBOFF2 24576
#define BUFB    43008
__global__ __launch_bounds__(512)
void k_conv_mma(){
    extern __shared__ __align__(128) char smem[];
    __shared__ __align__(8) unsigned long long mbars[4];
    unsigned usb = s2u(smem);
    unsigned umb = s2u(mbars);
    int tid = threadIdx.x, lane = tid & 31, wid = tid >> 5;
    int lq = lane >> 2, lr = lane & 3;
    int mw = wid >> 2, nw = wid & 3;
    int bid = blockIdx.x;
    int ht = bid % 14, d = (bid/14) & 31, b = bid / (14*32);
    int h0 = ht * 4;

    if (tid == 0){
#pragma unroll
        for (int i = 0; i < 4; i++)
            asm volatile("mbarrier.init.shared.b64 [%0], 1;" :: "r"(umb + i*8) : "memory");
    }
    __syncthreads();

    auto issue = [&](int s){
        int buf = s & 3;
        int ccg = s & 3, kh = (s >> 2) % 3, kd = s / 12;
        if (tid == 0)
            asm volatile("mbarrier.arrive.expect_tx.shared.b64 _, [%0], %1;"
                         :: "r"(umb + buf*8), "r"(43008u) : "memory");
        if (tid < 4){
            int r = tid;
            const unsigned* src = (const unsigned*)g_dwP +
                (((size_t)(b*34 + d + kd)*60 + (h0 + kh + r))*64 + ccg*16)*72;
            bulkcp(usb + (unsigned)(buf*BUFB + INBOFF2 + r*4608), src, 4608u, umb + buf*8);
        } else if (tid == 4){
            int s2 = (kd*3 + kh)*8 + ccg*2;
            bulkcp(usb + (unsigned)(buf*BUFB), g_wTh + (size_t)s2*3072, 24576u, umb + buf*8);
        }
    };

    float acc[2][7][4];
#pragma unroll
    for (int t = 0; t < 2; t++)
#pragma unroll
        for (int nt = 0; nt < 7; nt++)
#pragma unroll
            for (int j = 0; j < 4; j++) acc[t][nt][j] = 0.f;

    issue(0); issue(1); issue(2);
    for (int s = 0; s < 36; s++){
        if (s + 3 < 36) issue(s + 3);
        bwait(umb + (s&3)*8, (unsigned)((s >> 2) & 1));
        const char* buf = smem + (s&3)*BUFB;
#pragma unroll
        for (int ccq = 0; ccq < 2; ccq++){
            const uint4* wp = (const uint4*)(buf + ccq*12288);
            const unsigned* ibl = (const unsigned*)(buf + INBOFF2) + ((nw*16 + ccq*8 + lr)*72) + lq;
#pragma unroll
            for (int kw = 0; kw < 3; kw++){
                uint4 A0 = wp[(kw*8 + mw*2    )*32 + lane];
                uint4 A1 = wp[(kw*8 + mw*2 + 1)*32 + lane];
#pragma unroll
                for (int nt = 0; nt < 7; nt++){
                    unsigned b0 = ibl[nt*8 + kw];
                    unsigned b1 = ibl[nt*8 + kw + 288];
                    mma16f(acc[0][nt], A0, b0, b1);
                    mma16f(acc[1][nt], A1, b0, b1);
                }
            }
        }
        __syncthreads();
    }

    int h = h0 + nw;
#pragma unroll
    for (int t = 0; t < 2; t++){
        int o = (mw*2 + t)*16 + lq;
        float* base0 = g_x1c + ((size_t)(b*HIDc + o))*PP + (size_t)d*HW + h*56;
#pragma unroll
        for (int nt = 0; nt < 7; nt++){
            int w = nt*8 + 2*lr;
            float2 v0, v1;
            v0.x = fmaxf(acc[t][nt][0], 0.f); v0.y = fmaxf(acc[t][nt][1], 0.f);
            v1.x = fmaxf(acc[t][nt][2], 0.f); v1.y = fmaxf(acc[t][nt][3], 0.f);
            *(float2*)(base0 + w) = v0;
            *(float2*)(base0 + (size_t)8*PP + w) = v1;
        }
    }
}

// ---------------- K5: gate + proj_out via fp16 mma ----------------
#define FPAD 132
__global__ __launch_bounds__(256)
void k_final(float* __restrict__ out){
    __shared__ unsigned short sf[128*FPAD];
    int tid = threadIdx.x, lane = tid & 31, wid = tid >> 5;
    int lq = lane >> 2, lr = lane & 3;
    int mw = wid >> 2, nw = wid & 3;
    int b = blockIdx.y;
    int p0 = blockIdx.x*128;
    for (int i = tid; i < 16384; i += 256){
        int c = i >> 7, p = i & 127;
        int gp = p0 + p;
        int d = gp / HW;
        float v = g_x1c[((size_t)(b*HIDc + c))*PP + gp] * g_gate[(b*HIDc + c)*DDim + d];
        sf[c*FPAD + p] = __half_as_ushort(__float2half_rn(v));
    }
    __syncthreads();
    float acc[2][4][4];
#pragma unroll
    for (int t = 0; t < 2; t++)
#pragma unroll
        for (int nt = 0; nt < 4; nt++)
#pragma unroll
            for (int j = 0; j < 4; j++) acc[t][nt][j] = 0.f;
    const uint4* gA = (const uint4*)g_fA;
#pragma unroll
    for (int ks = 0; ks < 8; ks++){
        uint4 A0 = gA[((mw*2    )*8 + ks)*32 + lane];
        uint4 A1 = gA[((mw*2 + 1)*8 + ks)*32 + lane];
#pragma unroll
        for (int nt = 0; nt < 4; nt++){
            int p = nw*32 + nt*8 + lq;
            int c0 = ks*16 + 2*lr;
            unsigned b0 = (unsigned)sf[c0*FPAD + p]       | ((unsigned)sf[(c0+1)*FPAD + p] << 16);
            unsigned b1 = (unsigned)sf[(c0+8)*FPAD + p]   | ((unsigned)sf[(c0+9)*FPAD + p] << 16);
            mma16f(acc[0][nt], A0, b0, b1);
            mma16f(acc[1][nt], A1, b0, b1);
        }
    }
#pragma unroll
    for (int t = 0; t < 2; t++){
        int o = mw*32 + t*16 + lq;
        float* base = out + ((size_t)(b*64 + o))*PP + p0 + nw*32 + 2*lr;
#pragma unroll
        for (int nt = 0; nt < 4; nt++){
            float2 v0, v1;
            v0.x = acc[t][nt][0]; v0.y = acc[t][nt][1];
            v1.x = acc[t][nt][2]; v1.y = acc[t][nt][3];
            *(float2*)(base + nt*8) = v0;
            *(float2*)(base + (size_t)8*PP + nt*8) = v1;
        }
    }
}

// ---------------- launch ----------------
extern "C" void kernel_launch(void* const* d_in, const int* in_sizes, int n_in,
                              void* d_out, int out_size){
    const float* inp      = (const float*)d_in[0];
    const float* W_in     = (const float*)d_in[1];
    const float* W_dw     = (const float*)d_in[2];
    const float* W_s      = (const float*)d_in[3];
    const float* W_t1     = (const float*)d_in[4];
    const float* W_t2     = (const float*)d_in[5];
    const float* m_in_w   = (const float*)d_in[6];
    const float* m_conv_w = (const float*)d_in[7];
    const float* m_conv_b = (const float*)d_in[8];
    const float* m_x_w    = (const float*)d_in[9];
    const float* m_dt_w   = (const float*)d_in[10];
    const float* m_dt_b   = (const float*)d_in[11];
    const float* m_A_log  = (const float*)d_in[12];
    const float* m_D      = (const float*)d_in[13];
    const float* m_out_w  = (const float*)d_in[14];
    const float* W_out    = (const float*)d_in[15];
    float* out = (float*)d_out;

    cudaFuncSetAttribute(k_projT, cudaFuncAttributeMaxDynamicSharedMemorySize, 51200);
    cudaFuncSetAttribute(k_m3,    cudaFuncAttributeMaxDynamicSharedMemorySize, 19712*4);
    cudaFuncSetAttribute(k_conv_mma, cudaFuncAttributeMaxDynamicSharedMemorySize, 4*BUFB);

    k_wpack   <<<912, 256>>>(W_s, W_in, W_out);                   // idx 0
    k_projT   <<<dim3(784, Bb), 512, 51200>>>(inp);               // idx 1
    k_dw      <<<Bb*C2, 256>>>(W_dw);                             // idx 2
    k_conv_mma<<<Bb*DDim*14, 512, 4*BUFB>>>();                    // idx 3 (profiled slot)
    k_m1      <<<32, 256>>>(W_t1);
    k_m2      <<<128, 256>>>(m_in_w);
    k_m3      <<<Bb, 256, 19712*4>>>(m_conv_w, m_conv_b, m_x_w, m_dt_w,
                                     m_dt_b, m_A_log, m_D);
    k_m4      <<<64, 128>>>(m_out_w, W_t2);
    k_final   <<<dim3(784, Bb), 256>>>(out);
}

// round 16
// speedup vs baseline: 1.5248x; 1.0400x over previous
#include <cuda_runtime.h>
#include <cuda_fp16.h>
#include <math.h>
#include <stdint.h>

#define Bb   2
#define CIN  64
#define HIDc 128
#define C2   256
#define DDim 32
#define HHe  56
#define WWi  56
#define HW   3136
#define PP   100352

__device__ float g_xz [Bb*(size_t)C2*PP];
__device__ float g_x1c[Bb*(size_t)HIDc*PP];
__device__ float g_pool[Bb*HIDc*DDim];
__device__ float g_gate[Bb*HIDc*DDim];
// fully halo-padded fp16 x1: [b][dp 34][hp 60][cc 8][c2 8][ws 72] u32-pairs; pads stay zero
__device__ __align__(16) unsigned short g_dwP[(size_t)Bb*34*60*64*72*2];
// fp16 A-frag packed conv weights: [s2 72][kw 3][mt 8][lane 32][v 4] u32
__device__ __align__(16) unsigned g_wTh[72*3072];
// fp16 A-frag packed W_in: [ks 4][mt 16][lane 32][v 4] u32
__device__ __align__(16) unsigned g_pA[8192];
// fp16 A-frag packed W_out: [mt 4][ks 8][lane 32][v 4] u32
__device__ __align__(16) unsigned g_fA[4096];
// mamba intermediates
__device__ float g_seq[Bb*DDim*HIDc];
__device__ float g_xr [Bb*DDim*256];
__device__ float g_z  [Bb*DDim*256];
__device__ float g_y  [Bb*DDim*256];

__device__ __forceinline__ float sigmoidf_(float x){ return 1.f/(1.f+expf(-x)); }
__device__ __forceinline__ unsigned s2u(const void* p){ unsigned a; asm("{ .reg .u64 t; cvta.to.shared.u64 t, %1; cvt.u32.u64 %0, t; }" : "=r"(a) : "l"(p)); return a; }
__device__ __forceinline__ void bwait(unsigned a, unsigned par){
    asm volatile("{\n\t.reg .pred P;\n\tLW%=:\n\tmbarrier.try_wait.parity.acquire.cta.shared::cta.b64 P, [%0], %1, 0x989680;\n\t@P bra.uni LD%=;\n\tbra.uni LW%=;\n\tLD%=:\n\t}" :: "r"(a), "r"(par) : "memory");
}
__device__ __forceinline__ void bulkcp(unsigned dst, const void* src, unsigned bytes, unsigned mbar){
    asm volatile("cp.async.bulk.shared::cluster.global.mbarrier::complete_tx::bytes [%0], [%1], %2, [%3];"
                 :: "r"(dst), "l"(src), "r"(bytes), "r"(mbar) : "memory");
}
__device__ __forceinline__ void mma16f(float* c, const uint4 a, unsigned b0, unsigned b1){
    asm volatile("mma.sync.aligned.m16n8k16.row.col.f32.f16.f16.f32 "
                 "{%0,%1,%2,%3}, {%4,%5,%6,%7}, {%8,%9}, {%0,%1,%2,%3};"
                 : "+f"(c[0]), "+f"(c[1]), "+f"(c[2]), "+f"(c[3])
                 : "r"(a.x), "r"(a.y), "r"(a.z), "r"(a.w), "r"(b0), "r"(b1));
}

// ---------------- K0a: W_in pack (needed by k_projT) ----------------
__global__ __launch_bounds__(256)
void k_wpackA(const float* __restrict__ W_in){
    int i = blockIdx.x*256 + threadIdx.x;    // 8192
    int v = i & 3, lane = (i >> 2) & 31, mt = (i >> 7) & 15, ks = i >> 11;
    int o = mt*16 + (lane >> 2) + 8*(v & 1);
    int c = ks*16 + 2*(lane & 3) + 8*(v >> 1);
    __half2 h = __floats2half2_rn(W_in[o*CIN + c], W_in[o*CIN + c + 1]);
    g_pA[i] = *(unsigned*)&h;
}

// ---------------- K0b: conv Ws + W_out pack ----------------
__global__ __launch_bounds__(256)
void k_wpackB(const float* __restrict__ Ws, const float* __restrict__ W_out){
    int bid = blockIdx.x;
    if (bid < 864){
        int i = bid*256 + threadIdx.x;
        int v = i & 3, lane = (i >> 2) & 31, mt = (i >> 7) & 7, kw = (i >> 10) % 3, s2 = i / 3072;
        int kd = s2 / 24, kh = (s2 >> 3) % 3, cc = s2 & 7;
        int lq = lane >> 2, lr = lane & 3;
        int o  = mt*16 + lq + 8*(v & 1);
        int c0 = cc*16 + 2*lr + 8*(v >> 1);
        int t27 = kd*9 + kh*3 + kw;
        __half2 h = __floats2half2_rn(Ws[((size_t)o*HIDc + c0)*27 + t27],
                                      Ws[((size_t)o*HIDc + c0 + 1)*27 + t27]);
        g_wTh[i] = *(unsigned*)&h;
    } else {
        int i = (bid - 864)*256 + threadIdx.x;   // 4096
        int v = i & 3, lane = (i >> 2) & 31, ks = (i >> 7) & 7, mt = i >> 10;
        int o = mt*16 + (lane >> 2) + 8*(v & 1);
        int c = ks*16 + 2*(lane & 3) + 8*(v >> 1);
        __half2 h = __floats2half2_rn(W_out[o*HIDc + c], W_out[o*HIDc + c + 1]);
        g_fA[i] = *(unsigned*)&h;
    }
}

// ---------------- K1: proj_in via fp16 mma ----------------
__global__ __launch_bounds__(512)
void k_projT(const float* __restrict__ inp){
    extern __shared__ unsigned ps[];          // A 8192 u32 | B 4608 u32
    unsigned* sB = ps + 8192;
    uint4* sA4 = (uint4*)ps;
    int tid = threadIdx.x, lane = tid & 31, wid = tid >> 5;
    int lq = lane >> 2, lr = lane & 3;
    int mw = wid >> 2, nw = wid & 3;
    int b = blockIdx.y, p0 = blockIdx.x*128;
    const uint4* gA = (const uint4*)g_pA;
    for (int i = tid; i < 2048; i += 512) sA4[i] = gA[i];
    for (int i = tid; i < 4096; i += 512){
        int c2 = i >> 7, p = i & 127;
        float x0 = inp[((size_t)(b*CIN + 2*c2))*PP + p0 + p];
        float x1 = inp[((size_t)(b*CIN + 2*c2 + 1))*PP + p0 + p];
        __half2 h = __floats2half2_rn(x0, x1);
        sB[p*36 + c2] = *(unsigned*)&h;
    }
    __syncthreads();
    float acc[4][4][4];
#pragma unroll
    for (int t = 0; t < 4; t++)
#pragma unroll
        for (int nt = 0; nt < 4; nt++)
#pragma unroll
            for (int j = 0; j < 4; j++) acc[t][nt][j] = 0.f;
#pragma unroll
    for (int ks = 0; ks < 4; ks++){
        uint4 A[4];
#pragma unroll
        for (int t = 0; t < 4; t++) A[t] = sA4[(ks*16 + mw*4 + t)*32 + lane];
#pragma unroll
        for (int nt = 0; nt < 4; nt++){
            int pr = nw*32 + nt*8 + lq;
            unsigned b0 = sB[pr*36 + ks*8 + lr];
            unsigned b1 = sB[pr*36 + ks*8 + lr + 4];
#pragma unroll
            for (int t = 0; t < 4; t++) mma16f(acc[t][nt], A[t], b0, b1);
        }
    }
#pragma unroll
    for (int t = 0; t < 4; t++){
        int o = mw*64 + t*16 + lq;
        float* d0 = g_xz + ((size_t)(b*C2 + o))*PP + p0 + nw*32 + 2*lr;
#pragma unroll
        for (int nt = 0; nt < 4; nt++){
            float2 v0, v1;
            v0.x = acc[t][nt][0]; v0.y = acc[t][nt][1];
            v1.x = acc[t][nt][2]; v1.y = acc[t][nt][3];
            *(float2*)(d0 + nt*8) = v0;
            *(float2*)(d0 + (size_t)8*PP + nt*8) = v1;
        }
    }
}

// ---------------- K2: depthwise 3x3x3, rolling depth window ------------------
__global__ __launch_bounds__(256)
void k_dw(const float* __restrict__ W_dw){
    __shared__ float sp[3][60*58];
    __shared__ float red[8];
    int bid = blockIdx.x;
    int c = bid & 255, b = bid >> 8;
    int tid = threadIdx.x, lane = tid & 31, wid = tid >> 5;
    const float* src = g_xz + ((size_t)(b*C2 + c))*PP;
    float wv[27];
#pragma unroll
    for (int t = 0; t < 27; t++) wv[t] = W_dw[c*27 + t];

    auto load_plane = [&](int slot, int gd){
        if ((unsigned)gd < 32u){
            const float* p = src + gd*HW;
            for (int idx = tid; idx < 3480; idx += 256){
                int hh = idx / 60, ww = idx % 60;
                int gh = hh - 1, gw = ww - 1;
                float v = 0.f;
                if ((unsigned)gh < 56u && (unsigned)gw < 56u) v = p[gh*56 + gw];
                sp[slot][idx] = v;
            }
        } else {
            for (int idx = tid; idx < 3480; idx += 256) sp[slot][idx] = 0.f;
        }
    };
    load_plane(0, -1);
    load_plane(1, 0);
    load_plane(2, 1);

    int cidx = (c >> 4)*8 + ((c >> 1) & 7);
    bool isX1 = (c < HIDc);
    for (int d = 0; d < 32; d++){
        __syncthreads();
        float psum = 0.f;
        for (int idx = tid; idx < 784; idx += 256){
            int h = idx / 14, w0 = (idx % 14)*4;
            float a0 = 0.f, a1 = 0.f, a2 = 0.f, a3 = 0.f;
#pragma unroll
            for (int kd = 0; kd < 3; kd++){
                const float* pl = sp[(d + kd) % 3];
#pragma unroll
                for (int kh = 0; kh < 3; kh++){
                    const float* row = pl + (h + kh)*60 + w0;
                    float4 r03 = *(const float4*)row;
                    float2 r45 = *(const float2*)(row + 4);
                    float wA = wv[kd*9 + kh*3], wB = wv[kd*9 + kh*3 + 1], wC = wv[kd*9 + kh*3 + 2];
                    a0 += r03.x*wA + r03.y*wB + r03.z*wC;
                    a1 += r03.y*wA + r03.z*wB + r03.w*wC;
                    a2 += r03.z*wA + r03.w*wB + r45.x*wC;
                    a3 += r03.w*wA + r45.x*wB + r45.y*wC;
                }
            }
            if (isX1){
                size_t base = ((((size_t)((b*34 + d + 1)*60) + h + 1)*64 + cidx)*72 + w0 + 1)*2 + (c & 1);
                g_dwP[base]     = __half_as_ushort(__float2half_rn(a0));
                g_dwP[base + 2] = __half_as_ushort(__float2half_rn(a1));
                g_dwP[base + 4] = __half_as_ushort(__float2half_rn(a2));
                g_dwP[base + 6] = __half_as_ushort(__float2half_rn(a3));
            }
            psum += a0 + a1 + a2 + a3;
        }
        if (!isX1){
#pragma unroll
            for (int off = 16; off > 0; off >>= 1) psum += __shfl_xor_sync(0xffffffffu, psum, off);
            if (lane == 0) red[wid] = psum;
            __syncthreads();
            if (tid == 0){
                float s = 0.f;
#pragma unroll
                for (int i = 0; i < 8; i++) s += red[i];
                g_pool[(b*HIDc + (c - HIDc))*DDim + d] = s * (1.f/HW);
            }
        }
        __syncthreads();
        load_plane(d % 3, d + 2);
    }
}

// ---------------- mamba chain ----------------
__global__ __launch_bounds__(256)
void k_m1(const float* __restrict__ W_t1){
    int idx = blockIdx.x*256 + threadIdx.x;
    int i = idx & 127, t = (idx >> 7) & 31, b = idx >> 12;
    const float* w  = W_t1 + i*HIDc;
    const float* pl = g_pool + b*HIDc*DDim + t;
    float a = 0.f;
    for (int c = 0; c < HIDc; c++) a += w[c] * pl[c*DDim];
    g_seq[idx] = a;
}

__global__ __launch_bounds__(256)
void k_m2(const float* __restrict__ in_w){
    __shared__ float s[HIDc];
    int blk = blockIdx.x, tid = threadIdx.x;
    int half = blk & 1, t = (blk >> 1) & 31, b = blk >> 6;
    if (tid < HIDc) s[tid] = g_seq[(b*DDim + t)*HIDc + tid];
    __syncthreads();
    int j = half*256 + tid;
    const float* w = in_w + (size_t)j*HIDc;
    float a = 0.f;
#pragma unroll 4
    for (int i = 0; i < HIDc; i++) a += s[i]*w[i];
    if (half == 0) g_xr[(b*DDim + t)*256 + tid] = a;
    else           g_z [(b*DDim + t)*256 + tid] = a;
}

__global__ __launch_bounds__(256)
void k_m3(const float* __restrict__ conv_w, const float* __restrict__ conv_b,
          const float* __restrict__ x_w, const float* __restrict__ dt_w,
          const float* __restrict__ dt_b, const float* __restrict__ A_log,
          const float* __restrict__ Dp){
    extern __shared__ float sm[];
    float* s_x    = sm;
    float* s_proj = sm + 8192;
    float* s_u    = sm + 9472;
    int b = blockIdx.x, tid = threadIdx.x;
    for (int i = tid; i < 40*256; i += 256) s_u[i] = x_w[i];
    __syncthreads();
    for (int idx = tid; idx < DDim*256; idx += 256){
        int t = idx >> 8, j = idx & 255;
        float a = conv_b[j];
#pragma unroll
        for (int k = 0; k < 4; k++){
            int tt = t + k - 3;
            if (tt >= 0) a += g_xr[(b*DDim + tt)*256 + j] * conv_w[j*4 + k];
        }
        s_x[idx] = a * sigmoidf_(a);
    }
    __syncthreads();
    for (int idx = tid; idx < DDim*40; idx += 256){
        int t = idx / 40, q = idx % 40;
        float a = 0.f;
        const float* u = s_x + t*256;
        const float* w = s_u + q*256;
        for (int j = 0; j < 256; j++) a += u[j]*w[j];
        s_proj[idx] = a;
    }
    __syncthreads();
    for (int idx = tid; idx < DDim*256; idx += 256){
        int t = idx >> 8, j = idx & 255;
        float a = dt_b[j];
#pragma unroll
        for (int r = 0; r < 8; r++) a += s_proj[t*40 + r]*dt_w[j*8 + r];
        s_u[idx] = (a > 20.f) ? a : log1pf(expf(a));
    }
    __syncthreads();
    {
        int dch = tid;
        float A[16], h[16];
#pragma unroll
        for (int n = 0; n < 16; n++){ A[n] = -expf(A_log[dch*16 + n]); h[n] = 0.f; }
        float Dv = Dp[dch];
        for (int t = 0; t < DDim; t++){
            float dtv = s_u[t*256 + dch];
            float xv  = s_x[t*256 + dch];
            float y = 0.f;
#pragma unroll
            for (int n = 0; n < 16; n++){
                float dA = expf(dtv * A[n]);
                h[n] = dA*h[n] + dtv * s_proj[t*40 + 8 + n] * xv;
                y += h[n] * s_proj[t*40 + 24 + n];
            }
            y += xv * Dv;
            float zv = g_z[(b*DDim + t)*256 + dch];
            y *= zv * sigmoidf_(zv);
            g_y[(b*DDim + t)*256 + dch] = y;
        }
    }
}

__global__ __launch_bounds__(128)
void k_m4(const float* __restrict__ out_w, const float* __restrict__ W_t2){
    __shared__ float sy[256];
    __shared__ float som[HIDc];
    int bt = blockIdx.x, tid = threadIdx.x;
    int b = bt >> 5, t = bt & 31;
    sy[tid]       = g_y[bt*256 + tid];
    sy[tid + 128] = g_y[bt*256 + 128 + tid];
    __syncthreads();
    {
        const float* w = out_w + (size_t)tid*256;
        float a = 0.f;
#pragma unroll 4
        for (int j = 0; j < 256; j++) a += sy[j]*w[j];
        som[tid] = a;
    }
    __syncthreads();
    {
        const float* w = W_t2 + (size_t)tid*HIDc;
        float a = 0.f;
#pragma unroll 4
        for (int c = 0; c < HIDc; c++) a += som[c]*w[c];
        g_gate[(b*HIDc + tid)*DDim + t] = sigmoidf_(a);
    }
}

// ---------------- K4: fp16 mma conv, merged 64-ch stages (18 stages) ---------
// Stage s in [0,18): ccg = s&1 (64 channels), kh = (s>>1)%3, kd = s/6.
// Buffer: [weights 49152B (4 s2-blocks)][input 4 rows x 32 c2 x 72 u32 = 36864B]
#define INBOFF3 49152
#define BUFB    86016
__global__ __launch_bounds__(512)
void k_conv_mma(){
    extern __shared__ __align__(128) char smem[];
    __shared__ __align__(8) unsigned long long mbars[2];
    unsigned usb = s2u(smem);
    unsigned umb = s2u(mbars);
    int tid = threadIdx.x, lane = tid & 31, wid = tid >> 5;
    int lq = lane >> 2, lr = lane & 3;
    int mw = wid >> 2, nw = wid & 3;
    int bid = blockIdx.x;
    int ht = bid % 14, d = (bid/14) & 31, b = bid / (14*32);
    int h0 = ht * 4;

    if (tid == 0){
        asm volatile("mbarrier.init.shared.b64 [%0], 1;" :: "r"(umb) : "memory");
        asm volatile("mbarrier.init.shared.b64 [%0], 1;" :: "r"(umb + 8) : "memory");
    }
    __syncthreads();

    auto issue = [&](int s){
        int buf = s & 1;
        int ccg = s & 1, kh = (s >> 1) % 3, kd = s / 6;
        if (tid == 0)
            asm volatile("mbarrier.arrive.expect_tx.shared.b64 _, [%0], %1;"
                         :: "r"(umb + buf*8), "r"(86016u) : "memory");
        if (tid < 4){
            int r = tid;
            const unsigned* src = (const unsigned*)g_dwP +
                (((size_t)(b*34 + d + kd)*60 + (h0 + kh + r))*64 + ccg*32)*72;
            bulkcp(usb + (unsigned)(buf*BUFB + INBOFF3 + r*9216), src, 9216u, umb + buf*8);
        } else if (tid == 4){
            int s2 = (kd*3 + kh)*8 + ccg*4;
            bulkcp(usb + (unsigned)(buf*BUFB), g_wTh + (size_t)s2*3072, 49152u, umb + buf*8);
        }
    };

    float acc[2][7][4];
#pragma unroll
    for (int t = 0; t < 2; t++)
#pragma unroll
        for (int nt = 0; nt < 7; nt++)
#pragma unroll
            for (int j = 0; j < 4; j++) acc[t][nt][j] = 0.f;

    issue(0);
    for (int s = 0; s < 18; s++){
        if (s + 1 < 18) issue(s + 1);
        bwait(umb + (s&1)*8, (unsigned)((s >> 1) & 1));
        const char* buf = smem + (s&1)*BUFB;
#pragma unroll
        for (int ccq = 0; ccq < 4; ccq++){
            const uint4* wp = (const uint4*)(buf + ccq*12288);
            const unsigned* ibl = (const unsigned*)(buf + INBOFF3) + nw*9216/4 + (ccq*8 + lr)*72 + lq;
#pragma unroll
            for (int kw = 0; kw < 3; kw++){
                uint4 A0 = wp[(kw*8 + mw*2    )*32 + lane];
                uint4 A1 = wp[(kw*8 + mw*2 + 1)*32 + lane];
#pragma unroll
                for (int nt = 0; nt < 7; nt++){
                    unsigned b0 = ibl[nt*8 + kw];
                    unsigned b1 = ibl[nt*8 + kw + 288];
                    mma16f(acc[0][nt], A0, b0, b1);
                    mma16f(acc[1][nt], A1, b0, b1);
                }
            }
        }
        __syncthreads();
    }

    int h = h0 + nw;
#pragma unroll
    for (int t = 0; t < 2; t++){
        int o = (mw*2 + t)*16 + lq;
        float* base0 = g_x1c + ((size_t)(b*HIDc + o))*PP + (size_t)d*HW + h*56;
#pragma unroll
        for (int nt = 0; nt < 7; nt++){
            int w = nt*8 + 2*lr;
            float2 v0, v1;
            v0.x = fmaxf(acc[t][nt][0], 0.f); v0.y = fmaxf(acc[t][nt][1], 0.f);
            v1.x = fmaxf(acc[t][nt][2], 0.f); v1.y = fmaxf(acc[t][nt][3], 0.f);
            *(float2*)(base0 + w) = v0;
            *(float2*)(base0 + (size_t)8*PP + w) = v1;
        }
    }
}

// ---------------- K5: gate + proj_out via fp16 mma ----------------
#define FPAD 132
__global__ __launch_bounds__(256)
void k_final(float* __restrict__ out){
    __shared__ unsigned short sf[128*FPAD];
    int tid = threadIdx.x, lane = tid & 31, wid = tid >> 5;
    int lq = lane >> 2, lr = lane & 3;
    int mw = wid >> 2, nw = wid & 3;
    int b = blockIdx.y;
    int p0 = blockIdx.x*128;
    for (int i = tid; i < 16384; i += 256){
        int c = i >> 7, p = i & 127;
        int gp = p0 + p;
        int d = gp / HW;
        float v = g_x1c[((size_t)(b*HIDc + c))*PP + gp] * g_gate[(b*HIDc + c)*DDim + d];
        sf[c*FPAD + p] = __half_as_ushort(__float2half_rn(v));
    }
    __syncthreads();
    float acc[2][4][4];
#pragma unroll
    for (int t = 0; t < 2; t++)
#pragma unroll
        for (int nt = 0; nt < 4; nt++)
#pragma unroll
            for (int j = 0; j < 4; j++) acc[t][nt][j] = 0.f;
    const uint4* gA = (const uint4*)g_fA;
#pragma unroll
    for (int ks = 0; ks < 8; ks++){
        uint4 A0 = gA[((mw*2    )*8 + ks)*32 + lane];
        uint4 A1 = gA[((mw*2 + 1)*8 + ks)*32 + lane];
#pragma unroll
        for (int nt = 0; nt < 4; nt++){
            int p = nw*32 + nt*8 + lq;
            int c0 = ks*16 + 2*lr;
            unsigned b0 = (unsigned)sf[c0*FPAD + p]       | ((unsigned)sf[(c0+1)*FPAD + p] << 16);
            unsigned b1 = (unsigned)sf[(c0+8)*FPAD + p]   | ((unsigned)sf[(c0+9)*FPAD + p] << 16);
            mma16f(acc[0][nt], A0, b0, b1);
            mma16f(acc[1][nt], A1, b0, b1);
        }
    }
#pragma unroll
    for (int t = 0; t < 2; t++){
        int o = mw*32 + t*16 + lq;
        float* base = out + ((size_t)(b*64 + o))*PP + p0 + nw*32 + 2*lr;
#pragma unroll
        for (int nt = 0; nt < 4; nt++){
            float2 v0, v1;
            v0.x = acc[t][nt][0]; v0.y = acc[t][nt][1];
            v1.x = acc[t][nt][2]; v1.y = acc[t][nt][3];
            *(float2*)(base + nt*8) = v0;
            *(float2*)(base + (size_t)8*PP + nt*8) = v1;
        }
    }
}

// ---------------- launch ----------------
extern "C" void kernel_launch(void* const* d_in, const int* in_sizes, int n_in,
                              void* d_out, int out_size){
    const float* inp      = (const float*)d_in[0];
    const float* W_in     = (const float*)d_in[1];
    const float* W_dw     = (const float*)d_in[2];
    const float* W_s      = (const float*)d_in[3];
    const float* W_t1     = (const float*)d_in[4];
    const float* W_t2     = (const float*)d_in[5];
    const float* m_in_w   = (const float*)d_in[6];
    const float* m_conv_w = (const float*)d_in[7];
    const float* m_conv_b = (const float*)d_in[8];
    const float* m_x_w    = (const float*)d_in[9];
    const float* m_dt_w   = (const float*)d_in[10];
    const float* m_dt_b   = (const float*)d_in[11];
    const float* m_A_log  = (const float*)d_in[12];
    const float* m_D      = (const float*)d_in[13];
    const float* m_out_w  = (const float*)d_in[14];
    const float* W_out    = (const float*)d_in[15];
    float* out = (float*)d_out;

    cudaFuncSetAttribute(k_projT, cudaFuncAttributeMaxDynamicSharedMemorySize, 51200);
    cudaFuncSetAttribute(k_m3,    cudaFuncAttributeMaxDynamicSharedMemorySize, 19712*4);
    cudaFuncSetAttribute(k_conv_mma, cudaFuncAttributeMaxDynamicSharedMemorySize, 2*BUFB);

    k_wpackA  <<<32, 256>>>(W_in);                                // idx 0
    k_projT   <<<dim3(784, Bb), 512, 51200>>>(inp);               // idx 1
    k_wpackB  <<<880, 256>>>(W_s, W_out);                         // idx 2
    k_dw      <<<Bb*C2, 256>>>(W_dw);                             // idx 3 (profiled slot)
    k_conv_mma<<<Bb*DDim*14, 512, 2*BUFB>>>();                    // idx 4
    k_m1      <<<32, 256>>>(W_t1);
    k_m2      <<<128, 256>>>(m_in_w);
    k_m3      <<<Bb, 256, 19712*4>>>(m_conv_w, m_conv_b, m_x_w, m_dt_w,
                                     m_dt_b, m_A_log, m_D);
    k_m4      <<<64, 128>>>(m_out_w, W_t2);
    k_final   <<<dim3(784, Bb), 256>>>(out);
}